// round 1
// baseline (speedup 1.0000x reference)
#include <cuda_runtime.h>
#include <math.h>

// Problem constants
#define BSZ 2
#define TSEQ 2048
#define DMODEL 1024
#define NH 16
#define DK 64
#define BT (BSZ * TSEQ)          // 4096 rows

// Scratch (static __device__ arrays — no allocation allowed)
__device__ float g_qkv[BT * 3 * DMODEL];            // [4096, 3072]
__device__ float g_q[BSZ * NH * TSEQ * DK];         // [b,h,t,d]
__device__ float g_k[BSZ * NH * TSEQ * DK];
__device__ float g_v[BSZ * NH * TSEQ * DK];
__device__ float g_attn[BT * DMODEL];               // [b*t, h*d]

// ---------------------------------------------------------------------------
// Tiled SMEM GEMM with bias: C[M,N] = A[M,K] @ B[K,N] + bias[N]
// 128x128 block tile, BK=16, 256 threads, 8x8 microtile.
// M,N,K all multiples of tile dims for this problem (no bounds checks).
// ---------------------------------------------------------------------------
template<int BM, int BN, int BK>
__global__ __launch_bounds__(256)
void gemm_bias_kernel(const float* __restrict__ A,
                      const float* __restrict__ B,
                      const float* __restrict__ bias,
                      float* __restrict__ C,
                      int M, int N, int K)
{
    __shared__ float As[BK][BM + 4];   // padded to dodge store conflicts
    __shared__ float Bs[BK][BN];

    const int tid = threadIdx.x;
    const int bm = blockIdx.y * BM;
    const int bn = blockIdx.x * BN;
    const int ty = tid / 16;           // 16x16 thread grid
    const int tx = tid % 16;

    float acc[8][8];
    #pragma unroll
    for (int i = 0; i < 8; i++)
        #pragma unroll
        for (int j = 0; j < 8; j++) acc[i][j] = 0.f;

    for (int k0 = 0; k0 < K; k0 += BK) {
        // Load A tile (BM x BK), store transposed As[k][m]
        #pragma unroll
        for (int i = 0; i < (BM * BK) / (256 * 4); i++) {
            int j  = tid + i * 256;           // float4 index
            int r  = j / (BK / 4);
            int c4 = j % (BK / 4);
            float4 v = *(const float4*)&A[(size_t)(bm + r) * K + k0 + c4 * 4];
            As[c4 * 4 + 0][r] = v.x;
            As[c4 * 4 + 1][r] = v.y;
            As[c4 * 4 + 2][r] = v.z;
            As[c4 * 4 + 3][r] = v.w;
        }
        // Load B tile (BK x BN)
        #pragma unroll
        for (int i = 0; i < (BK * BN) / (256 * 4); i++) {
            int j  = tid + i * 256;
            int r  = j / (BN / 4);
            int c4 = j % (BN / 4);
            *(float4*)&Bs[r][c4 * 4] =
                *(const float4*)&B[(size_t)(k0 + r) * N + bn + c4 * 4];
        }
        __syncthreads();

        #pragma unroll
        for (int k = 0; k < BK; k++) {
            float a[8], b[8];
            *(float4*)&a[0] = *(const float4*)&As[k][ty * 8];
            *(float4*)&a[4] = *(const float4*)&As[k][ty * 8 + 4];
            *(float4*)&b[0] = *(const float4*)&Bs[k][tx * 8];
            *(float4*)&b[4] = *(const float4*)&Bs[k][tx * 8 + 4];
            #pragma unroll
            for (int i = 0; i < 8; i++)
                #pragma unroll
                for (int j = 0; j < 8; j++)
                    acc[i][j] += a[i] * b[j];
        }
        __syncthreads();
    }

    // Epilogue: add bias, write
    #pragma unroll
    for (int i = 0; i < 8; i++) {
        int r = bm + ty * 8 + i;
        #pragma unroll
        for (int j = 0; j < 8; j += 4) {
            int c = bn + tx * 8 + j;
            float4 o;
            o.x = acc[i][j + 0] + bias[c + 0];
            o.y = acc[i][j + 1] + bias[c + 1];
            o.z = acc[i][j + 2] + bias[c + 2];
            o.w = acc[i][j + 3] + bias[c + 3];
            *(float4*)&C[(size_t)r * N + c] = o;
        }
    }
}

// ---------------------------------------------------------------------------
// RoPE + split/relayout: g_qkv[4096,3072] -> g_q/g_k (rope'd), g_v
// Layout target: [b, h, t, d]. One thread per (even,odd) pair.
// ---------------------------------------------------------------------------
__global__ void rope_split_kernel()
{
    const int NP = BSZ * TSEQ * 3 * NH * (DK / 2);
    int idx = blockIdx.x * blockDim.x + threadIdx.x;
    if (idx >= NP) return;

    int d2 = idx % (DK / 2);
    int h  = (idx / (DK / 2)) % NH;
    int qi = (idx / ((DK / 2) * NH)) % 3;
    int t  = (idx / ((DK / 2) * NH * 3)) % TSEQ;
    int b  = idx / ((DK / 2) * NH * 3 * TSEQ);

    size_t src = (size_t)(b * TSEQ + t) * (3 * DMODEL) + qi * DMODEL + h * DK + 2 * d2;
    float x1 = g_qkv[src];
    float x2 = g_qkv[src + 1];

    float* dst = (qi == 0) ? g_q : (qi == 1) ? g_k : g_v;
    size_t o = (size_t)((b * NH + h) * TSEQ + t) * DK + 2 * d2;

    if (qi < 2) {
        float inv_freq = powf(10000.f, -((float)(2 * d2)) / (float)DK);
        float ang = (float)t * inv_freq;
        float s, c;
        sincosf(ang, &s, &c);
        dst[o]     = x1 * c - x2 * s;
        dst[o + 1] = x1 * s + x2 * c;
    } else {
        dst[o]     = x1;
        dst[o + 1] = x2;
    }
}

// ---------------------------------------------------------------------------
// Flash attention (causal, online softmax), fp32.
// Block: 256 threads, one 64-query tile per block, kv tiles 0..q_tile.
// Output directly in [b*t, h*64+d] layout for the out-proj GEMM.
// ---------------------------------------------------------------------------
#define FA_PAD 68   // 64 + 4 floats row stride (keeps float4 alignment)

__global__ __launch_bounds__(256)
void flash_kernel(float* __restrict__ outp)
{
    extern __shared__ float sm[];
    float* Qs = sm;                   // [64][68]
    float* Ks = Qs + 64 * FA_PAD;
    float* Vs = Ks + 64 * FA_PAD;
    float* Ss = Vs + 64 * FA_PAD;

    const int tid = threadIdx.x;
    const int qt  = blockIdx.y;       // query tile index (0..31)
    const int bh  = blockIdx.z;       // b*NH + h
    const int b = bh / NH, h = bh % NH;

    const float* Qp = g_q + (size_t)bh * TSEQ * DK;
    const float* Kp = g_k + (size_t)bh * TSEQ * DK;
    const float* Vp = g_v + (size_t)bh * TSEQ * DK;
    const int qbase = qt * 64;

    // Load Q tile (64x64 -> 1024 float4s / 256 threads = 4 each)
    #pragma unroll
    for (int i = 0; i < 4; i++) {
        int j = tid + i * 256;
        int r = j >> 4, d4 = j & 15;
        *(float4*)&Qs[r * FA_PAD + d4 * 4] =
            *(const float4*)&Qp[(size_t)(qbase + r) * DK + d4 * 4];
    }

    const int row = tid >> 2;         // 0..63 (softmax/PV mapping)
    const int sub = tid & 3;          // 4 threads per row, 16 cols each
    const int r0 = (tid / 16) * 4;    // S-compute mapping: 4x4 microtile
    const int c0 = (tid % 16) * 4;

    float O[16];
    #pragma unroll
    for (int i = 0; i < 16; i++) O[i] = 0.f;
    float m = -INFINITY, l = 0.f;

    for (int j = 0; j <= qt; j++) {
        __syncthreads();   // prev PV done + Q loaded before overwriting K/V
        // Load K, V tiles
        #pragma unroll
        for (int i = 0; i < 4; i++) {
            int jj = tid + i * 256;
            int r = jj >> 4, d4 = jj & 15;
            *(float4*)&Ks[r * FA_PAD + d4 * 4] =
                *(const float4*)&Kp[(size_t)(j * 64 + r) * DK + d4 * 4];
            *(float4*)&Vs[r * FA_PAD + d4 * 4] =
                *(const float4*)&Vp[(size_t)(j * 64 + r) * DK + d4 * 4];
        }
        __syncthreads();

        // S = Q K^T (4x4 per thread), scale, causal mask on diagonal tile
        float acc[4][4];
        #pragma unroll
        for (int i = 0; i < 4; i++)
            #pragma unroll
            for (int c = 0; c < 4; c++) acc[i][c] = 0.f;

        #pragma unroll
        for (int k = 0; k < 64; k += 4) {
            float4 q[4], kk[4];
            #pragma unroll
            for (int i = 0; i < 4; i++)
                q[i] = *(const float4*)&Qs[(r0 + i) * FA_PAD + k];
            #pragma unroll
            for (int i = 0; i < 4; i++)
                kk[i] = *(const float4*)&Ks[(c0 + i) * FA_PAD + k];
            #pragma unroll
            for (int i = 0; i < 4; i++)
                #pragma unroll
                for (int c = 0; c < 4; c++)
                    acc[i][c] += q[i].x * kk[c].x + q[i].y * kk[c].y +
                                 q[i].z * kk[c].z + q[i].w * kk[c].w;
        }

        const bool diag = (j == qt);
        #pragma unroll
        for (int i = 0; i < 4; i++)
            #pragma unroll
            for (int c = 0; c < 4; c++) {
                float sv = acc[i][c] * 0.125f;  // 1/sqrt(64)
                if (diag && (j * 64 + c0 + c) > (qbase + r0 + i))
                    sv = -INFINITY;
                Ss[(r0 + i) * FA_PAD + c0 + c] = sv;
            }
        __syncthreads();

        // Online softmax (4 threads per row, 16 cols each)
        float rmax = -INFINITY;
        #pragma unroll
        for (int c = 0; c < 16; c++)
            rmax = fmaxf(rmax, Ss[row * FA_PAD + sub * 16 + c]);
        rmax = fmaxf(rmax, __shfl_xor_sync(0xffffffffu, rmax, 1));
        rmax = fmaxf(rmax, __shfl_xor_sync(0xffffffffu, rmax, 2));

        float mnew  = fmaxf(m, rmax);
        float alpha = expf(m - mnew);   // 0 on first tile (m = -inf)
        float rsum  = 0.f;
        #pragma unroll
        for (int c = 0; c < 16; c++) {
            float p = expf(Ss[row * FA_PAD + sub * 16 + c] - mnew);
            Ss[row * FA_PAD + sub * 16 + c] = p;
            rsum += p;
        }
        rsum += __shfl_xor_sync(0xffffffffu, rsum, 1);
        rsum += __shfl_xor_sync(0xffffffffu, rsum, 2);
        l = l * alpha + rsum;
        m = mnew;
        #pragma unroll
        for (int i = 0; i < 16; i++) O[i] *= alpha;
        __syncwarp();   // P writes by own quad visible before PV reads

        // O += P @ V  (V addresses are row-independent -> smem broadcast)
        #pragma unroll 4
        for (int s = 0; s < 64; s++) {
            float p = Ss[row * FA_PAD + s];
            float4 v0 = *(const float4*)&Vs[s * FA_PAD + sub * 16 + 0];
            float4 v1 = *(const float4*)&Vs[s * FA_PAD + sub * 16 + 4];
            float4 v2 = *(const float4*)&Vs[s * FA_PAD + sub * 16 + 8];
            float4 v3 = *(const float4*)&Vs[s * FA_PAD + sub * 16 + 12];
            O[0]  += p * v0.x; O[1]  += p * v0.y; O[2]  += p * v0.z; O[3]  += p * v0.w;
            O[4]  += p * v1.x; O[5]  += p * v1.y; O[6]  += p * v1.z; O[7]  += p * v1.w;
            O[8]  += p * v2.x; O[9]  += p * v2.y; O[10] += p * v2.z; O[11] += p * v2.w;
            O[12] += p * v3.x; O[13] += p * v3.y; O[14] += p * v3.z; O[15] += p * v3.w;
        }
    }

    const float inv_l = 1.f / l;
    #pragma unroll
    for (int i = 0; i < 16; i++) O[i] *= inv_l;

    const size_t orow = (size_t)(b * TSEQ + qbase + row);
    const int ocol = h * DK + sub * 16;
    *(float4*)&outp[orow * DMODEL + ocol + 0]  = make_float4(O[0],  O[1],  O[2],  O[3]);
    *(float4*)&outp[orow * DMODEL + ocol + 4]  = make_float4(O[4],  O[5],  O[6],  O[7]);
    *(float4*)&outp[orow * DMODEL + ocol + 8]  = make_float4(O[8],  O[9],  O[10], O[11]);
    *(float4*)&outp[orow * DMODEL + ocol + 12] = make_float4(O[12], O[13], O[14], O[15]);
}

// ---------------------------------------------------------------------------
// Launch
// ---------------------------------------------------------------------------
extern "C" void kernel_launch(void* const* d_in, const int* in_sizes, int n_in,
                              void* d_out, int out_size)
{
    const float* x     = (const float*)d_in[0];   // [2,2048,1024]
    const float* W_qkv = (const float*)d_in[1];   // [1024,3072]
    const float* b_qkv = (const float*)d_in[2];   // [3072]
    const float* W_out = (const float*)d_in[3];   // [1024,1024]
    const float* b_out = (const float*)d_in[4];   // [1024]
    float* out = (float*)d_out;                   // [2,2048,1024]

    float* qkv;   cudaGetSymbolAddress((void**)&qkv,  g_qkv);
    float* attn;  cudaGetSymbolAddress((void**)&attn, g_attn);

    // 1) QKV projection: [4096,1024] @ [1024,3072] + bias
    {
        dim3 grid(3 * DMODEL / 128, BT / 128);
        gemm_bias_kernel<128, 128, 16><<<grid, 256>>>(x, W_qkv, b_qkv, qkv,
                                                      BT, 3 * DMODEL, DMODEL);
    }

    // 2) RoPE + split into [b,h,t,d]
    {
        const int NP = BSZ * TSEQ * 3 * NH * (DK / 2);
        rope_split_kernel<<<(NP + 255) / 256, 256>>>();
    }

    // 3) Causal flash attention -> g_attn in [b*t, h*64+d]
    {
        const int smem = 4 * 64 * FA_PAD * sizeof(float);  // 69632 B
        cudaFuncSetAttribute(flash_kernel,
                             cudaFuncAttributeMaxDynamicSharedMemorySize, smem);
        dim3 grid(1, TSEQ / 64, BSZ * NH);
        flash_kernel<<<grid, 256, smem>>>(attn);
    }

    // 4) Output projection: [4096,1024] @ [1024,1024] + bias -> d_out
    {
        dim3 grid(DMODEL / 128, BT / 128);
        gemm_bias_kernel<128, 128, 16><<<grid, 256>>>(attn, W_out, b_out, out,
                                                      BT, DMODEL, DMODEL);
    }
}

// round 2
// speedup vs baseline: 8.2958x; 8.2958x over previous
#include <cuda_runtime.h>
#include <cuda_fp16.h>
#include <math.h>

#define BSZ 2
#define TSEQ 2048
#define DMODEL 1024
#define NH 16
#define DK 64
#define BT (BSZ * TSEQ)          // 4096

// ---------------- scratch ----------------
__device__ float  g_qkv[BT * 3 * DMODEL];                 // fp32 qkv
__device__ __half g_xh[BT * DMODEL];                      // x fp16
__device__ __half g_wqkvT[3 * DMODEL * DMODEL];           // [3072][1024]
__device__ __half g_woutT[DMODEL * DMODEL];               // [1024][1024]
__device__ __half g_qh[BSZ * NH * TSEQ * DK];             // [bh][t][d]
__device__ __half g_kh[BSZ * NH * TSEQ * DK];
__device__ __half g_vh[BSZ * NH * TSEQ * DK];
__device__ __half g_attn[BT * DMODEL];                    // [b*t][h*64+d] fp16

// SW128-style swizzle: row stride 128B (64 halves), 16B chunks
__device__ __forceinline__ unsigned swz(unsigned row, unsigned chunk) {
    return row * 128u + ((chunk ^ (row & 7u)) << 4);
}

__device__ __forceinline__ void mma_f16(float* c, unsigned a0, unsigned a1,
                                        unsigned a2, unsigned a3,
                                        unsigned b0, unsigned b1) {
    asm volatile(
        "mma.sync.aligned.m16n8k16.row.col.f32.f16.f16.f32 "
        "{%0,%1,%2,%3}, {%4,%5,%6,%7}, {%8,%9}, {%0,%1,%2,%3};\n"
        : "+f"(c[0]), "+f"(c[1]), "+f"(c[2]), "+f"(c[3])
        : "r"(a0), "r"(a1), "r"(a2), "r"(a3), "r"(b0), "r"(b1));
}

__device__ __forceinline__ unsigned pack_h2(float a, float b) {
    __half2 h = __floats2half2_rn(a, b);
    return *reinterpret_cast<unsigned*>(&h);
}

// ---------------------------------------------------------------------------
// prep kernels
// ---------------------------------------------------------------------------
__global__ void cast_x_kernel(const float* __restrict__ x) {
    int i = blockIdx.x * blockDim.x + threadIdx.x;     // half2 index
    if (i >= BT * DMODEL / 2) return;
    float2 v = ((const float2*)x)[i];
    ((__half2*)g_xh)[i] = __floats2half2_rn(v.x, v.y);
}

// W [K=1024][N] -> Wt [N][K] fp16
__global__ void transpose_cast_kernel(const float* __restrict__ W,
                                      __half* __restrict__ Wt, int N) {
    __shared__ float tile[32][33];
    int n0 = blockIdx.x * 32, k0 = blockIdx.y * 32;
    int tx = threadIdx.x, ty = threadIdx.y;            // 32 x 8
    #pragma unroll
    for (int i = 0; i < 4; i++)
        tile[ty + i * 8][tx] = W[(size_t)(k0 + ty + i * 8) * N + n0 + tx];
    __syncthreads();
    #pragma unroll
    for (int i = 0; i < 4; i++)
        Wt[(size_t)(n0 + ty + i * 8) * DMODEL + k0 + tx] =
            __float2half(tile[tx][ty + i * 8]);
}

// ---------------------------------------------------------------------------
// fp16 tensor-core GEMM: C[M,N] = A[M,K] @ Bt[N,K]^T + bias, C fp32
// 128x128 tile, BK=64, 256 threads (8 warps, 2x4), warp tile 64x32
// ---------------------------------------------------------------------------
__global__ __launch_bounds__(256)
void gemm_h_kernel(const __half* __restrict__ A, const __half* __restrict__ Bt,
                   const float* __restrict__ bias, float* __restrict__ C,
                   int M, int N, int K)
{
    __shared__ char Asb[128 * 128];   // 128 rows x 64 halves swizzled
    __shared__ char Bsb[128 * 128];

    const int tid = threadIdx.x;
    const int wid = tid >> 5, lane = tid & 31;
    const int g = lane >> 2, t = lane & 3;
    const int bm = blockIdx.y * 128, bn = blockIdx.x * 128;
    const int wm = (wid & 1) * 64, wn = (wid >> 1) * 32;

    float acc[4][4][4];
    #pragma unroll
    for (int i = 0; i < 4; i++)
        #pragma unroll
        for (int j = 0; j < 4; j++)
            #pragma unroll
            for (int r = 0; r < 4; r++) acc[i][j][r] = 0.f;

    for (int k0 = 0; k0 < K; k0 += 64) {
        __syncthreads();
        #pragma unroll
        for (int p = 0; p < 4; p++) {
            int idx = tid + p * 256;
            int r = idx >> 3, c8 = idx & 7;
            *(uint4*)(Asb + swz(r, c8)) =
                *(const uint4*)&A[(size_t)(bm + r) * K + k0 + c8 * 8];
            *(uint4*)(Bsb + swz(r, c8)) =
                *(const uint4*)&Bt[(size_t)(bn + r) * K + k0 + c8 * 8];
        }
        __syncthreads();

        #pragma unroll
        for (int kk = 0; kk < 4; kk++) {
            unsigned af[4][4], bf[4][2];
            #pragma unroll
            for (int mt = 0; mt < 4; mt++) {
                unsigned r1 = wm + mt * 16 + g, r2 = r1 + 8;
                af[mt][0] = *(unsigned*)(Asb + swz(r1, 2 * kk) + 4 * t);
                af[mt][1] = *(unsigned*)(Asb + swz(r2, 2 * kk) + 4 * t);
                af[mt][2] = *(unsigned*)(Asb + swz(r1, 2 * kk + 1) + 4 * t);
                af[mt][3] = *(unsigned*)(Asb + swz(r2, 2 * kk + 1) + 4 * t);
            }
            #pragma unroll
            for (int nt = 0; nt < 4; nt++) {
                unsigned nr = wn + nt * 8 + g;
                bf[nt][0] = *(unsigned*)(Bsb + swz(nr, 2 * kk) + 4 * t);
                bf[nt][1] = *(unsigned*)(Bsb + swz(nr, 2 * kk + 1) + 4 * t);
            }
            #pragma unroll
            for (int mt = 0; mt < 4; mt++)
                #pragma unroll
                for (int nt = 0; nt < 4; nt++)
                    mma_f16(acc[mt][nt], af[mt][0], af[mt][1], af[mt][2],
                            af[mt][3], bf[nt][0], bf[nt][1]);
        }
    }

    #pragma unroll
    for (int mt = 0; mt < 4; mt++) {
        int row = bm + wm + mt * 16 + g;
        #pragma unroll
        for (int nt = 0; nt < 4; nt++) {
            int col = bn + wn + nt * 8 + 2 * t;
            float b0 = bias[col], b1 = bias[col + 1];
            float2 s0 = make_float2(acc[mt][nt][0] + b0, acc[mt][nt][1] + b1);
            float2 s1 = make_float2(acc[mt][nt][2] + b0, acc[mt][nt][3] + b1);
            *(float2*)&C[(size_t)row * N + col] = s0;
            *(float2*)&C[(size_t)(row + 8) * N + col] = s1;
        }
    }
}

// ---------------------------------------------------------------------------
// RoPE + split to fp16 [bh][t][d]
// ---------------------------------------------------------------------------
__global__ void rope_split_kernel()
{
    const int NP = BSZ * TSEQ * 3 * NH * (DK / 2);
    int idx = blockIdx.x * blockDim.x + threadIdx.x;
    if (idx >= NP) return;

    int d2 = idx % (DK / 2);
    int h  = (idx / (DK / 2)) % NH;
    int qi = (idx / ((DK / 2) * NH)) % 3;
    int t  = (idx / ((DK / 2) * NH * 3)) % TSEQ;
    int b  = idx / ((DK / 2) * NH * 3 * TSEQ);

    size_t src = (size_t)(b * TSEQ + t) * (3 * DMODEL) + qi * DMODEL + h * DK + 2 * d2;
    float x1 = g_qkv[src];
    float x2 = g_qkv[src + 1];

    __half* dst = (qi == 0) ? g_qh : (qi == 1) ? g_kh : g_vh;
    size_t o = (size_t)((b * NH + h) * TSEQ + t) * DK + 2 * d2;

    if (qi < 2) {
        float inv_freq = powf(10000.f, -((float)(2 * d2)) / (float)DK);
        float ang = (float)t * inv_freq;
        float s, c;
        sincosf(ang, &s, &c);
        *(__half2*)&dst[o] = __floats2half2_rn(x1 * c - x2 * s, x1 * s + x2 * c);
    } else {
        *(__half2*)&dst[o] = __floats2half2_rn(x1, x2);
    }
}

// ---------------------------------------------------------------------------
// Flash attention, fp16 mma. 128-row Q tile, 64-col KV tiles, 8 warps.
// ---------------------------------------------------------------------------
__global__ __launch_bounds__(256)
void flash_h_kernel()
{
    __shared__ char Qsb[128 * 128];   // 128 x 64 halves
    __shared__ char Ksb[64 * 128];    // 64 x 64
    __shared__ char Vtb[64 * 128];    // V^T: [d][s]

    const int tid = threadIdx.x;
    const int wid = tid >> 5, lane = tid & 31;
    const int g = lane >> 2, t = lane & 3;
    const int qx = gridDim.x - 1 - blockIdx.x;     // big tiles first
    const int bh = blockIdx.y;
    const int b = bh >> 4, h = bh & 15;
    const int qb = qx * 128;

    const __half* Qp = g_qh + (size_t)bh * TSEQ * DK;
    const __half* Kp = g_kh + (size_t)bh * TSEQ * DK;
    const __half* Vp = g_vh + (size_t)bh * TSEQ * DK;

    // Load Q tile swizzled
    #pragma unroll
    for (int p = 0; p < 4; p++) {
        int idx = tid + p * 256;
        int r = idx >> 3, c8 = idx & 7;
        *(uint4*)(Qsb + swz(r, c8)) =
            *(const uint4*)&Qp[(size_t)(qb + r) * DK + c8 * 8];
    }
    __syncthreads();

    // Q fragments (persistent)
    unsigned qa[4][4];
    {
        unsigned r1 = wid * 16 + g, r2 = r1 + 8;
        #pragma unroll
        for (int kk = 0; kk < 4; kk++) {
            qa[kk][0] = *(unsigned*)(Qsb + swz(r1, 2 * kk) + 4 * t);
            qa[kk][1] = *(unsigned*)(Qsb + swz(r2, 2 * kk) + 4 * t);
            qa[kk][2] = *(unsigned*)(Qsb + swz(r1, 2 * kk + 1) + 4 * t);
            qa[kk][3] = *(unsigned*)(Qsb + swz(r2, 2 * kk + 1) + 4 * t);
        }
    }

    float o[8][4];
    #pragma unroll
    for (int nt = 0; nt < 8; nt++)
        #pragma unroll
        for (int r = 0; r < 4; r++) o[nt][r] = 0.f;
    float m0 = -INFINITY, m1 = -INFINITY, l0 = 0.f, l1 = 0.f;
    const float scale = 0.125f;   // 1/sqrt(64)
    const int tiles = 2 * qx + 2;

    for (int j = 0; j < tiles; j++) {
        __syncthreads();
        // K tile (row-major swizzled)
        #pragma unroll
        for (int p = 0; p < 2; p++) {
            int idx = tid + p * 256;
            int r = idx >> 3, c8 = idx & 7;
            *(uint4*)(Ksb + swz(r, c8)) =
                *(const uint4*)&Kp[(size_t)(j * 64 + r) * DK + c8 * 8];
        }
        // V tile transposed into Vtb[d][s]
        #pragma unroll
        for (int p = 0; p < 2; p++) {
            int idx = tid + p * 256;
            int s = idx >> 3, d0 = (idx & 7) * 8;
            uint4 v = *(const uint4*)&Vp[(size_t)(j * 64 + s) * DK + d0];
            const __half* hv = (const __half*)&v;
            unsigned base = ((unsigned)s >> 3);
            #pragma unroll
            for (int i = 0; i < 8; i++)
                *(__half*)(Vtb + (d0 + i) * 128 + ((base ^ (unsigned)i) << 4)
                           + (s & 7) * 2) = hv[i];
        }
        __syncthreads();

        // S = Q K^T
        float sa[8][4];
        #pragma unroll
        for (int nt = 0; nt < 8; nt++)
            #pragma unroll
            for (int r = 0; r < 4; r++) sa[nt][r] = 0.f;
        #pragma unroll
        for (int kk = 0; kk < 4; kk++)
            #pragma unroll
            for (int nt = 0; nt < 8; nt++) {
                unsigned nr = nt * 8 + g;
                unsigned b0 = *(unsigned*)(Ksb + swz(nr, 2 * kk) + 4 * t);
                unsigned b1 = *(unsigned*)(Ksb + swz(nr, 2 * kk + 1) + 4 * t);
                mma_f16(sa[nt], qa[kk][0], qa[kk][1], qa[kk][2], qa[kk][3], b0, b1);
            }

        // causal mask (only last two tiles of each q-tile need it)
        if (j >= 2 * qx) {
            int row0 = qb + wid * 16 + g, row1 = row0 + 8;
            #pragma unroll
            for (int nt = 0; nt < 8; nt++) {
                int c = j * 64 + nt * 8 + 2 * t;
                if (c > row0)     sa[nt][0] = -1e30f;
                if (c + 1 > row0) sa[nt][1] = -1e30f;
                if (c > row1)     sa[nt][2] = -1e30f;
                if (c + 1 > row1) sa[nt][3] = -1e30f;
            }
        }

        // row max (raw units) over quad
        float rm0 = -INFINITY, rm1 = -INFINITY;
        #pragma unroll
        for (int nt = 0; nt < 8; nt++) {
            rm0 = fmaxf(rm0, fmaxf(sa[nt][0], sa[nt][1]));
            rm1 = fmaxf(rm1, fmaxf(sa[nt][2], sa[nt][3]));
        }
        rm0 = fmaxf(rm0, __shfl_xor_sync(0xffffffffu, rm0, 1));
        rm0 = fmaxf(rm0, __shfl_xor_sync(0xffffffffu, rm0, 2));
        rm1 = fmaxf(rm1, __shfl_xor_sync(0xffffffffu, rm1, 1));
        rm1 = fmaxf(rm1, __shfl_xor_sync(0xffffffffu, rm1, 2));

        float M0 = fmaxf(m0, rm0), M1 = fmaxf(m1, rm1);
        float a0 = __expf((m0 - M0) * scale);
        float a1 = __expf((m1 - M1) * scale);

        unsigned pa[8], pb[8];
        float rs0 = 0.f, rs1 = 0.f;
        #pragma unroll
        for (int nt = 0; nt < 8; nt++) {
            float p00 = __expf((sa[nt][0] - M0) * scale);
            float p01 = __expf((sa[nt][1] - M0) * scale);
            float p10 = __expf((sa[nt][2] - M1) * scale);
            float p11 = __expf((sa[nt][3] - M1) * scale);
            rs0 += p00 + p01;
            rs1 += p10 + p11;
            pa[nt] = pack_h2(p00, p01);
            pb[nt] = pack_h2(p10, p11);
        }
        rs0 += __shfl_xor_sync(0xffffffffu, rs0, 1);
        rs0 += __shfl_xor_sync(0xffffffffu, rs0, 2);
        rs1 += __shfl_xor_sync(0xffffffffu, rs1, 1);
        rs1 += __shfl_xor_sync(0xffffffffu, rs1, 2);
        l0 = l0 * a0 + rs0;
        l1 = l1 * a1 + rs1;
        m0 = M0; m1 = M1;

        #pragma unroll
        for (int nt = 0; nt < 8; nt++) {
            o[nt][0] *= a0; o[nt][1] *= a0;
            o[nt][2] *= a1; o[nt][3] *= a1;
        }

        // O += P @ V   (P fragments come straight from S accum layout)
        #pragma unroll
        for (int kk = 0; kk < 4; kk++) {
            unsigned A0 = pa[2 * kk], A1 = pb[2 * kk];
            unsigned A2 = pa[2 * kk + 1], A3 = pb[2 * kk + 1];
            #pragma unroll
            for (int nt = 0; nt < 8; nt++) {
                unsigned nr = nt * 8 + g;
                unsigned b0 = *(unsigned*)(Vtb + swz(nr, 2 * kk) + 4 * t);
                unsigned b1 = *(unsigned*)(Vtb + swz(nr, 2 * kk + 1) + 4 * t);
                mma_f16(o[nt], A0, A1, A2, A3, b0, b1);
            }
        }
    }

    float i0 = 1.f / l0, i1 = 1.f / l1;
    int row0 = qb + wid * 16 + g;
    size_t gr0 = (size_t)(b * TSEQ + row0) * DMODEL;
    size_t gr1 = (size_t)(b * TSEQ + row0 + 8) * DMODEL;
    #pragma unroll
    for (int nt = 0; nt < 8; nt++) {
        int col = h * DK + nt * 8 + 2 * t;
        *(__half2*)&g_attn[gr0 + col] = __floats2half2_rn(o[nt][0] * i0, o[nt][1] * i0);
        *(__half2*)&g_attn[gr1 + col] = __floats2half2_rn(o[nt][2] * i1, o[nt][3] * i1);
    }
}

// ---------------------------------------------------------------------------
extern "C" void kernel_launch(void* const* d_in, const int* in_sizes, int n_in,
                              void* d_out, int out_size)
{
    const float* x     = (const float*)d_in[0];
    const float* W_qkv = (const float*)d_in[1];
    const float* b_qkv = (const float*)d_in[2];
    const float* W_out = (const float*)d_in[3];
    const float* b_out = (const float*)d_in[4];
    float* out = (float*)d_out;

    float*  qkv;    cudaGetSymbolAddress((void**)&qkv,    g_qkv);
    __half* xh;     cudaGetSymbolAddress((void**)&xh,     g_xh);
    __half* wqkvT;  cudaGetSymbolAddress((void**)&wqkvT,  g_wqkvT);
    __half* woutT;  cudaGetSymbolAddress((void**)&woutT,  g_woutT);
    __half* attn;   cudaGetSymbolAddress((void**)&attn,   g_attn);

    // prep: casts + weight transposes
    cast_x_kernel<<<(BT * DMODEL / 2 + 255) / 256, 256>>>(x);
    {
        dim3 grid(3 * DMODEL / 32, DMODEL / 32), blk(32, 8);
        transpose_cast_kernel<<<grid, blk>>>(W_qkv, wqkvT, 3 * DMODEL);
    }
    {
        dim3 grid(DMODEL / 32, DMODEL / 32), blk(32, 8);
        transpose_cast_kernel<<<grid, blk>>>(W_out, woutT, DMODEL);
    }

    // 1) QKV projection (fp16 mma, fp32 out)
    {
        dim3 grid(3 * DMODEL / 128, BT / 128);
        gemm_h_kernel<<<grid, 256>>>(xh, wqkvT, b_qkv, qkv, BT, 3 * DMODEL, DMODEL);
    }

    // 2) RoPE + split to fp16
    {
        const int NP = BSZ * TSEQ * 3 * NH * (DK / 2);
        rope_split_kernel<<<(NP + 255) / 256, 256>>>();
    }

    // 3) flash attention (fp16 mma)
    {
        dim3 grid(TSEQ / 128, BSZ * NH);
        flash_h_kernel<<<grid, 256>>>();
    }

    // 4) output projection
    {
        dim3 grid(DMODEL / 128, BT / 128);
        gemm_h_kernel<<<grid, 256>>>(attn, woutT, b_out, out, BT, DMODEL, DMODEL);
    }
}

// round 3
// speedup vs baseline: 9.7468x; 1.1749x over previous
#include <cuda_runtime.h>
#include <cuda_fp16.h>
#include <math.h>

#define BSZ 2
#define TSEQ 2048
#define DMODEL 1024
#define NH 16
#define DK 64
#define BT (BSZ * TSEQ)          // 4096

// ---------------- scratch ----------------
__device__ float  g_qkv[BT * 3 * DMODEL];
__device__ __half g_xh[BT * DMODEL];
__device__ __half g_wqkvT[3 * DMODEL * DMODEL];           // [3072][1024]
__device__ __half g_woutT[DMODEL * DMODEL];               // [1024][1024]
__device__ __half g_qh[BSZ * NH * TSEQ * DK];
__device__ __half g_kh[BSZ * NH * TSEQ * DK];
__device__ __half g_vh[BSZ * NH * TSEQ * DK];
__device__ __half g_attn[BT * DMODEL];

// swizzle: 64-half rows (128B), 16B chunks
__device__ __forceinline__ unsigned swz(unsigned row, unsigned chunk) {
    return row * 128u + ((chunk ^ (row & 7u)) << 4);
}
__device__ __forceinline__ unsigned smaddr(const void* p) {
    return (unsigned)__cvta_generic_to_shared(p);
}
__device__ __forceinline__ void cp16(unsigned s, const void* g) {
    asm volatile("cp.async.cg.shared.global [%0], [%1], 16;\n" :: "r"(s), "l"(g));
}
__device__ __forceinline__ void cp_commit() {
    asm volatile("cp.async.commit_group;\n" ::);
}
__device__ __forceinline__ void cp_wait0() { asm volatile("cp.async.wait_group 0;\n" ::); }
__device__ __forceinline__ void cp_wait1() { asm volatile("cp.async.wait_group 1;\n" ::); }

__device__ __forceinline__ void ldsm4(unsigned* r, unsigned a) {
    asm volatile("ldmatrix.sync.aligned.m8n8.x4.shared.b16 {%0,%1,%2,%3}, [%4];\n"
                 : "=r"(r[0]), "=r"(r[1]), "=r"(r[2]), "=r"(r[3]) : "r"(a));
}
__device__ __forceinline__ void ldsm4t(unsigned* r, unsigned a) {
    asm volatile("ldmatrix.sync.aligned.m8n8.x4.trans.shared.b16 {%0,%1,%2,%3}, [%4];\n"
                 : "=r"(r[0]), "=r"(r[1]), "=r"(r[2]), "=r"(r[3]) : "r"(a));
}
__device__ __forceinline__ void mma_f16(float* c, unsigned a0, unsigned a1,
                                        unsigned a2, unsigned a3,
                                        unsigned b0, unsigned b1) {
    asm volatile(
        "mma.sync.aligned.m16n8k16.row.col.f32.f16.f16.f32 "
        "{%0,%1,%2,%3}, {%4,%5,%6,%7}, {%8,%9}, {%0,%1,%2,%3};\n"
        : "+f"(c[0]), "+f"(c[1]), "+f"(c[2]), "+f"(c[3])
        : "r"(a0), "r"(a1), "r"(a2), "r"(a3), "r"(b0), "r"(b1));
}
__device__ __forceinline__ unsigned pack_h2(float a, float b) {
    __half2 h = __floats2half2_rn(a, b);
    return *reinterpret_cast<unsigned*>(&h);
}

// ---------------------------------------------------------------------------
// prep
// ---------------------------------------------------------------------------
__global__ void cast_x_kernel(const float* __restrict__ x) {
    int i = blockIdx.x * blockDim.x + threadIdx.x;
    if (i >= BT * DMODEL / 2) return;
    float2 v = ((const float2*)x)[i];
    ((__half2*)g_xh)[i] = __floats2half2_rn(v.x, v.y);
}

__global__ void transpose_cast_kernel(const float* __restrict__ W,
                                      __half* __restrict__ Wt, int N) {
    __shared__ float tile[32][33];
    int n0 = blockIdx.x * 32, k0 = blockIdx.y * 32;
    int tx = threadIdx.x, ty = threadIdx.y;
    #pragma unroll
    for (int i = 0; i < 4; i++)
        tile[ty + i * 8][tx] = W[(size_t)(k0 + ty + i * 8) * N + n0 + tx];
    __syncthreads();
    #pragma unroll
    for (int i = 0; i < 4; i++)
        Wt[(size_t)(n0 + ty + i * 8) * DMODEL + k0 + tx] =
            __float2half(tile[tx][ty + i * 8]);
}

// ---------------------------------------------------------------------------
// GEMM: C[M,N] = A[M,K] @ Bt[N,K]^T + bias.  128x128 tile, BK=64,
// cp.async double-buffered, ldmatrix fragments, 8 warps (2x4), warp 64x32.
// ---------------------------------------------------------------------------
__global__ __launch_bounds__(256)
void gemm_h_kernel(const __half* __restrict__ A, const __half* __restrict__ Bt,
                   const float* __restrict__ bias, float* __restrict__ C,
                   int M, int N, int K)
{
    extern __shared__ __align__(16) char sm[];
    // layout: A stage0 16K, A stage1 16K, B stage0 16K, B stage1 16K
    char* As[2] = { sm, sm + 16384 };
    char* Bs[2] = { sm + 32768, sm + 49152 };

    const int tid = threadIdx.x;
    const int wid = tid >> 5, lane = tid & 31;
    const int g = lane >> 2, t = lane & 3;
    const int bm = blockIdx.y * 128, bn = blockIdx.x * 128;
    const int wm = (wid & 1) * 64, wn = (wid >> 1) * 32;

    const int lr = tid >> 1;                 // loader row 0..127
    const int lc = (tid & 1) * 4;            // loader chunk base (4 chunks each)

    float acc[4][4][4];
    #pragma unroll
    for (int i = 0; i < 4; i++)
        #pragma unroll
        for (int j = 0; j < 4; j++)
            #pragma unroll
            for (int r = 0; r < 4; r++) acc[i][j][r] = 0.f;

    const int KT = K / 64;

    // prologue: stage 0
    {
        unsigned sa = smaddr(As[0]), sb = smaddr(Bs[0]);
        #pragma unroll
        for (int c = 0; c < 4; c++) {
            cp16(sa + swz(lr, lc + c), &A[(size_t)(bm + lr) * K + (lc + c) * 8]);
            cp16(sb + swz(lr, lc + c), &Bt[(size_t)(bn + lr) * K + (lc + c) * 8]);
        }
        cp_commit();
    }

    for (int kt = 0; kt < KT; kt++) {
        __syncthreads();   // buffer (kt+1)&1 free (readers of kt-1 done)
        if (kt + 1 < KT) {
            int st = (kt + 1) & 1, k0 = (kt + 1) * 64;
            unsigned sa = smaddr(As[st]), sb = smaddr(Bs[st]);
            #pragma unroll
            for (int c = 0; c < 4; c++) {
                cp16(sa + swz(lr, lc + c), &A[(size_t)(bm + lr) * K + k0 + (lc + c) * 8]);
                cp16(sb + swz(lr, lc + c), &Bt[(size_t)(bn + lr) * K + k0 + (lc + c) * 8]);
            }
            cp_commit();
            cp_wait1();
        } else {
            cp_wait0();
        }
        __syncthreads();

        const unsigned sa = smaddr(As[kt & 1]), sb = smaddr(Bs[kt & 1]);
        const unsigned arow = ((lane >> 3) & 1) * 8 + (lane & 7);
        const unsigned ach  = (lane >> 4);
        const unsigned brow = (lane >> 4) * 8 + (lane & 7);
        const unsigned bch  = (lane >> 3) & 1;

        #pragma unroll
        for (int kk = 0; kk < 4; kk++) {
            unsigned af[4][4], bf[2][4];
            #pragma unroll
            for (int mt = 0; mt < 4; mt++)
                ldsm4(af[mt], sa + swz(wm + mt * 16 + arow, 2 * kk + ach));
            #pragma unroll
            for (int np = 0; np < 2; np++)
                ldsm4(bf[np], sb + swz(wn + np * 16 + brow, 2 * kk + bch));
            #pragma unroll
            for (int mt = 0; mt < 4; mt++)
                #pragma unroll
                for (int nt = 0; nt < 4; nt++)
                    mma_f16(acc[mt][nt], af[mt][0], af[mt][1], af[mt][2], af[mt][3],
                            bf[nt >> 1][(nt & 1) * 2], bf[nt >> 1][(nt & 1) * 2 + 1]);
        }
    }

    #pragma unroll
    for (int mt = 0; mt < 4; mt++) {
        int row = bm + wm + mt * 16 + g;
        #pragma unroll
        for (int nt = 0; nt < 4; nt++) {
            int col = bn + wn + nt * 8 + 2 * t;
            float b0 = bias[col], b1 = bias[col + 1];
            *(float2*)&C[(size_t)row * N + col] =
                make_float2(acc[mt][nt][0] + b0, acc[mt][nt][1] + b1);
            *(float2*)&C[(size_t)(row + 8) * N + col] =
                make_float2(acc[mt][nt][2] + b0, acc[mt][nt][3] + b1);
        }
    }
}

// ---------------------------------------------------------------------------
// RoPE + split
// ---------------------------------------------------------------------------
__global__ void rope_split_kernel()
{
    const int NP = BSZ * TSEQ * 3 * NH * (DK / 2);
    int idx = blockIdx.x * blockDim.x + threadIdx.x;
    if (idx >= NP) return;

    int d2 = idx % (DK / 2);
    int h  = (idx / (DK / 2)) % NH;
    int qi = (idx / ((DK / 2) * NH)) % 3;
    int t  = (idx / ((DK / 2) * NH * 3)) % TSEQ;
    int b  = idx / ((DK / 2) * NH * 3 * TSEQ);

    size_t src = (size_t)(b * TSEQ + t) * (3 * DMODEL) + qi * DMODEL + h * DK + 2 * d2;
    float x1 = g_qkv[src];
    float x2 = g_qkv[src + 1];

    __half* dst = (qi == 0) ? g_qh : (qi == 1) ? g_kh : g_vh;
    size_t o = (size_t)((b * NH + h) * TSEQ + t) * DK + 2 * d2;

    if (qi < 2) {
        float inv_freq = powf(10000.f, -((float)(2 * d2)) / (float)DK);
        float ang = (float)t * inv_freq;
        float s, c;
        sincosf(ang, &s, &c);
        *(__half2*)&dst[o] = __floats2half2_rn(x1 * c - x2 * s, x1 * s + x2 * c);
    } else {
        *(__half2*)&dst[o] = __floats2half2_rn(x1, x2);
    }
}

// ---------------------------------------------------------------------------
// Flash attention: 128-q tile, 64-kv tiles, cp.async double-buffered K/V,
// ldmatrix (trans for V). 8 warps, each 16 q-rows.
// ---------------------------------------------------------------------------
__global__ __launch_bounds__(256)
void flash_h_kernel()
{
    extern __shared__ __align__(16) char sm[];
    char* Qs = sm;                               // 16KB (128x64)
    char* Ks[2] = { sm + 16384, sm + 24576 };    // 8KB each (64x64)
    char* Vs[2] = { sm + 32768, sm + 40960 };

    const int tid = threadIdx.x;
    const int wid = tid >> 5, lane = tid & 31;
    const int g = lane >> 2, t = lane & 3;
    const int qx = gridDim.x - 1 - blockIdx.x;   // big tiles first
    const int bh = blockIdx.y;
    const int b = bh >> 4, h = bh & 15;
    const int qb = qx * 128;

    const __half* Qp = g_qh + (size_t)bh * TSEQ * DK;
    const __half* Kp = g_kh + (size_t)bh * TSEQ * DK;
    const __half* Vp = g_vh + (size_t)bh * TSEQ * DK;

    const int lr  = tid >> 1;                    // 0..127 (Q loader)
    const int lc  = (tid & 1) * 4;
    const int kvr = tid >> 2;                    // 0..63 (KV loader)
    const int kvc = (tid & 3) * 2;

    // Q tile + KV stage 0
    {
        unsigned sq = smaddr(Qs);
        #pragma unroll
        for (int c = 0; c < 4; c++)
            cp16(sq + swz(lr, lc + c), &Qp[(size_t)(qb + lr) * DK + (lc + c) * 8]);
        cp_commit();
        unsigned sk = smaddr(Ks[0]), sv = smaddr(Vs[0]);
        #pragma unroll
        for (int c = 0; c < 2; c++) {
            cp16(sk + swz(kvr, kvc + c), &Kp[(size_t)kvr * DK + (kvc + c) * 8]);
            cp16(sv + swz(kvr, kvc + c), &Vp[(size_t)kvr * DK + (kvc + c) * 8]);
        }
        cp_commit();
    }

    unsigned qa[4][4];
    float o[8][4];
    #pragma unroll
    for (int nt = 0; nt < 8; nt++)
        #pragma unroll
        for (int r = 0; r < 4; r++) o[nt][r] = 0.f;
    float m0 = -INFINITY, m1 = -INFINITY, l0 = 0.f, l1 = 0.f;
    const float scale = 0.125f;
    const int tiles = 2 * qx + 2;

    const unsigned arow = ((lane >> 3) & 1) * 8 + (lane & 7);
    const unsigned ach  = (lane >> 4);
    const unsigned brow = (lane >> 4) * 8 + (lane & 7);
    const unsigned bch  = (lane >> 3) & 1;

    for (int j = 0; j < tiles; j++) {
        __syncthreads();
        if (j + 1 < tiles) {
            int st = (j + 1) & 1, s0 = (j + 1) * 64;
            unsigned sk = smaddr(Ks[st]), sv = smaddr(Vs[st]);
            #pragma unroll
            for (int c = 0; c < 2; c++) {
                cp16(sk + swz(kvr, kvc + c), &Kp[(size_t)(s0 + kvr) * DK + (kvc + c) * 8]);
                cp16(sv + swz(kvr, kvc + c), &Vp[(size_t)(s0 + kvr) * DK + (kvc + c) * 8]);
            }
            cp_commit();
            cp_wait1();
        } else {
            cp_wait0();
        }
        __syncthreads();

        if (j == 0) {   // Q fragments (Q group completed with stage 0)
            unsigned sq = smaddr(Qs);
            #pragma unroll
            for (int kk = 0; kk < 4; kk++)
                ldsm4(qa[kk], sq + swz(wid * 16 + arow, 2 * kk + ach));
        }

        const unsigned sk = smaddr(Ks[j & 1]), sv = smaddr(Vs[j & 1]);

        // S = Q K^T
        float sa[8][4];
        #pragma unroll
        for (int nt = 0; nt < 8; nt++)
            #pragma unroll
            for (int r = 0; r < 4; r++) sa[nt][r] = 0.f;
        #pragma unroll
        for (int kk = 0; kk < 4; kk++) {
            unsigned kf[4][4];
            #pragma unroll
            for (int np = 0; np < 4; np++)
                ldsm4(kf[np], sk + swz(np * 16 + brow, 2 * kk + bch));
            #pragma unroll
            for (int nt = 0; nt < 8; nt++)
                mma_f16(sa[nt], qa[kk][0], qa[kk][1], qa[kk][2], qa[kk][3],
                        kf[nt >> 1][(nt & 1) * 2], kf[nt >> 1][(nt & 1) * 2 + 1]);
        }

        if (j >= 2 * qx) {
            int row0 = qb + wid * 16 + g, row1 = row0 + 8;
            #pragma unroll
            for (int nt = 0; nt < 8; nt++) {
                int c = j * 64 + nt * 8 + 2 * t;
                if (c > row0)     sa[nt][0] = -1e30f;
                if (c + 1 > row0) sa[nt][1] = -1e30f;
                if (c > row1)     sa[nt][2] = -1e30f;
                if (c + 1 > row1) sa[nt][3] = -1e30f;
            }
        }

        float rm0 = -INFINITY, rm1 = -INFINITY;
        #pragma unroll
        for (int nt = 0; nt < 8; nt++) {
            rm0 = fmaxf(rm0, fmaxf(sa[nt][0], sa[nt][1]));
            rm1 = fmaxf(rm1, fmaxf(sa[nt][2], sa[nt][3]));
        }
        rm0 = fmaxf(rm0, __shfl_xor_sync(0xffffffffu, rm0, 1));
        rm0 = fmaxf(rm0, __shfl_xor_sync(0xffffffffu, rm0, 2));
        rm1 = fmaxf(rm1, __shfl_xor_sync(0xffffffffu, rm1, 1));
        rm1 = fmaxf(rm1, __shfl_xor_sync(0xffffffffu, rm1, 2));

        float M0 = fmaxf(m0, rm0), M1 = fmaxf(m1, rm1);
        float a0 = __expf((m0 - M0) * scale);
        float a1 = __expf((m1 - M1) * scale);

        unsigned pa[8], pb[8];
        float rs0 = 0.f, rs1 = 0.f;
        #pragma unroll
        for (int nt = 0; nt < 8; nt++) {
            float p00 = __expf((sa[nt][0] - M0) * scale);
            float p01 = __expf((sa[nt][1] - M0) * scale);
            float p10 = __expf((sa[nt][2] - M1) * scale);
            float p11 = __expf((sa[nt][3] - M1) * scale);
            rs0 += p00 + p01;
            rs1 += p10 + p11;
            pa[nt] = pack_h2(p00, p01);
            pb[nt] = pack_h2(p10, p11);
        }
        rs0 += __shfl_xor_sync(0xffffffffu, rs0, 1);
        rs0 += __shfl_xor_sync(0xffffffffu, rs0, 2);
        rs1 += __shfl_xor_sync(0xffffffffu, rs1, 1);
        rs1 += __shfl_xor_sync(0xffffffffu, rs1, 2);
        l0 = l0 * a0 + rs0;
        l1 = l1 * a1 + rs1;
        m0 = M0; m1 = M1;

        #pragma unroll
        for (int nt = 0; nt < 8; nt++) {
            o[nt][0] *= a0; o[nt][1] *= a0;
            o[nt][2] *= a1; o[nt][3] *= a1;
        }

        // O += P @ V  (V^T fragments via ldmatrix.trans on row-major V tile)
        #pragma unroll
        for (int kk = 0; kk < 4; kk++) {
            unsigned vf[4][4];
            #pragma unroll
            for (int np = 0; np < 4; np++)
                ldsm4t(vf[np], sv + swz(16 * kk + arow, np * 2 + ach));
            unsigned A0 = pa[2 * kk], A1 = pb[2 * kk];
            unsigned A2 = pa[2 * kk + 1], A3 = pb[2 * kk + 1];
            #pragma unroll
            for (int nt = 0; nt < 8; nt++)
                mma_f16(o[nt], A0, A1, A2, A3,
                        vf[nt >> 1][(nt & 1) * 2], vf[nt >> 1][(nt & 1) * 2 + 1]);
        }
    }

    float i0 = 1.f / l0, i1 = 1.f / l1;
    int row0 = qb + wid * 16 + g;
    size_t gr0 = (size_t)(b * TSEQ + row0) * DMODEL;
    size_t gr1 = (size_t)(b * TSEQ + row0 + 8) * DMODEL;
    #pragma unroll
    for (int nt = 0; nt < 8; nt++) {
        int col = h * DK + nt * 8 + 2 * t;
        *(__half2*)&g_attn[gr0 + col] = __floats2half2_rn(o[nt][0] * i0, o[nt][1] * i0);
        *(__half2*)&g_attn[gr1 + col] = __floats2half2_rn(o[nt][2] * i1, o[nt][3] * i1);
    }
}

// ---------------------------------------------------------------------------
extern "C" void kernel_launch(void* const* d_in, const int* in_sizes, int n_in,
                              void* d_out, int out_size)
{
    const float* x     = (const float*)d_in[0];
    const float* W_qkv = (const float*)d_in[1];
    const float* b_qkv = (const float*)d_in[2];
    const float* W_out = (const float*)d_in[3];
    const float* b_out = (const float*)d_in[4];
    float* out = (float*)d_out;

    float*  qkv;    cudaGetSymbolAddress((void**)&qkv,    g_qkv);
    __half* xh;     cudaGetSymbolAddress((void**)&xh,     g_xh);
    __half* wqkvT;  cudaGetSymbolAddress((void**)&wqkvT,  g_wqkvT);
    __half* woutT;  cudaGetSymbolAddress((void**)&woutT,  g_woutT);
    __half* attn;   cudaGetSymbolAddress((void**)&attn,   g_attn);

    static bool attr_set = false;
    if (!attr_set) {
        cudaFuncSetAttribute(gemm_h_kernel,
                             cudaFuncAttributeMaxDynamicSharedMemorySize, 65536);
        cudaFuncSetAttribute(flash_h_kernel,
                             cudaFuncAttributeMaxDynamicSharedMemorySize, 49152);
        attr_set = true;
    }

    cast_x_kernel<<<(BT * DMODEL / 2 + 255) / 256, 256>>>(x);
    {
        dim3 grid(3 * DMODEL / 32, DMODEL / 32), blk(32, 8);
        transpose_cast_kernel<<<grid, blk>>>(W_qkv, wqkvT, 3 * DMODEL);
    }
    {
        dim3 grid(DMODEL / 32, DMODEL / 32), blk(32, 8);
        transpose_cast_kernel<<<grid, blk>>>(W_out, woutT, DMODEL);
    }

    // 1) QKV projection
    {
        dim3 grid(3 * DMODEL / 128, BT / 128);
        gemm_h_kernel<<<grid, 256, 65536>>>(xh, wqkvT, b_qkv, qkv, BT, 3 * DMODEL, DMODEL);
    }

    // 2) RoPE + split
    {
        const int NP = BSZ * TSEQ * 3 * NH * (DK / 2);
        rope_split_kernel<<<(NP + 255) / 256, 256>>>();
    }

    // 3) flash attention
    {
        dim3 grid(TSEQ / 128, BSZ * NH);
        flash_h_kernel<<<grid, 256, 49152>>>();
    }

    // 4) output projection
    {
        dim3 grid(DMODEL / 128, BT / 128);
        gemm_h_kernel<<<grid, 256, 65536>>>(attn, woutT, b_out, out, BT, DMODEL, DMODEL);
    }
}

// round 5
// speedup vs baseline: 10.1906x; 1.0455x over previous
#include <cuda_runtime.h>
#include <cuda_fp16.h>
#include <math.h>

#define BSZ 2
#define TSEQ 2048
#define DMODEL 1024
#define NH 16
#define DK 64
#define BT (BSZ * TSEQ)          // 4096
#define GEMM_KT 16               // K=1024 / BK=64 for both projections

// ---------------- scratch ----------------
__device__ __half g_xh[BT * DMODEL];
__device__ __half g_wqkvT[3 * DMODEL * DMODEL];           // [3072][1024]
__device__ __half g_woutT[DMODEL * DMODEL];               // [1024][1024]
__device__ __half g_qh[BSZ * NH * TSEQ * DK];             // [bh][t][d]
__device__ __half g_kh[BSZ * NH * TSEQ * DK];
__device__ __half g_vh[BSZ * NH * TSEQ * DK];
__device__ __half g_attn[BT * DMODEL];
__device__ float2 g_rope[TSEQ * 32];                      // (cos,sin) per (t, d2)

// swizzle: 64-half rows (128B), 16B chunks
__device__ __forceinline__ unsigned swz(unsigned row, unsigned chunk) {
    return row * 128u + ((chunk ^ (row & 7u)) << 4);
}
__device__ __forceinline__ unsigned smaddr(const void* p) {
    return (unsigned)__cvta_generic_to_shared(p);
}
__device__ __forceinline__ void cp16(unsigned s, const void* g) {
    asm volatile("cp.async.cg.shared.global [%0], [%1], 16;\n" :: "r"(s), "l"(g));
}
__device__ __forceinline__ void cp_commit() { asm volatile("cp.async.commit_group;\n" ::); }
__device__ __forceinline__ void cp_wait0() { asm volatile("cp.async.wait_group 0;\n" ::); }
__device__ __forceinline__ void cp_wait1() { asm volatile("cp.async.wait_group 1;\n" ::); }

__device__ __forceinline__ void ldsm4(unsigned* r, unsigned a) {
    asm volatile("ldmatrix.sync.aligned.m8n8.x4.shared.b16 {%0,%1,%2,%3}, [%4];\n"
                 : "=r"(r[0]), "=r"(r[1]), "=r"(r[2]), "=r"(r[3]) : "r"(a));
}
__device__ __forceinline__ void ldsm4t(unsigned* r, unsigned a) {
    asm volatile("ldmatrix.sync.aligned.m8n8.x4.trans.shared.b16 {%0,%1,%2,%3}, [%4];\n"
                 : "=r"(r[0]), "=r"(r[1]), "=r"(r[2]), "=r"(r[3]) : "r"(a));
}
__device__ __forceinline__ void mma_f16(float* c, unsigned a0, unsigned a1,
                                        unsigned a2, unsigned a3,
                                        unsigned b0, unsigned b1) {
    asm volatile(
        "mma.sync.aligned.m16n8k16.row.col.f32.f16.f16.f32 "
        "{%0,%1,%2,%3}, {%4,%5,%6,%7}, {%8,%9}, {%0,%1,%2,%3};\n"
        : "+f"(c[0]), "+f"(c[1]), "+f"(c[2]), "+f"(c[3])
        : "r"(a0), "r"(a1), "r"(a2), "r"(a3), "r"(b0), "r"(b1));
}
__device__ __forceinline__ unsigned pack_h2(float a, float b) {
    __half2 h = __floats2half2_rn(a, b);
    return *reinterpret_cast<unsigned*>(&h);
}

// ---------------------------------------------------------------------------
// prep
// ---------------------------------------------------------------------------
__global__ void cast_x_kernel(const float* __restrict__ x) {
    int i = blockIdx.x * blockDim.x + threadIdx.x;
    if (i >= BT * DMODEL / 2) return;
    float2 v = ((const float2*)x)[i];
    ((__half2*)g_xh)[i] = __floats2half2_rn(v.x, v.y);
}

__global__ void rope_table_kernel() {
    int i = blockIdx.x * blockDim.x + threadIdx.x;   // TSEQ*32
    if (i >= TSEQ * 32) return;
    int tt = i >> 5, d2 = i & 31;
    float invf = exp2f(-(float)(2 * d2) * 0.20762050593046f);  // log2(1e4)/64
    float s, c;
    sincosf((float)tt * invf, &s, &c);
    g_rope[i] = make_float2(c, s);
}

__global__ void transpose_cast_kernel(const float* __restrict__ W,
                                      __half* __restrict__ Wt, int N) {
    __shared__ float tile[32][33];
    int n0 = blockIdx.x * 32, k0 = blockIdx.y * 32;
    int tx = threadIdx.x, ty = threadIdx.y;
    #pragma unroll
    for (int i = 0; i < 4; i++)
        tile[ty + i * 8][tx] = W[(size_t)(k0 + ty + i * 8) * N + n0 + tx];
    __syncthreads();
    #pragma unroll
    for (int i = 0; i < 4; i++)
        Wt[(size_t)(n0 + ty + i * 8) * DMODEL + k0 + tx] =
            __float2half(tile[tx][ty + i * 8]);
}

// ---------------------------------------------------------------------------
// GEMM: C = A[M,1024] @ Bt[N,1024]^T (+bias). 128x128 tile, BK=64, 3-stage
// cp.async pipeline, single barrier per stage. 8 warps (2x4), warp 64x32.
// mode 0: fp32 C + bias.  mode 1: QKV epilogue (bias + RoPE + split, fp16).
// ---------------------------------------------------------------------------
__global__ __launch_bounds__(256)
void gemm_h_kernel(const __half* __restrict__ A, const __half* __restrict__ Bt,
                   const float* __restrict__ bias, float* __restrict__ C,
                   int M, int N, int mode)
{
    extern __shared__ __align__(16) char sm[];
    // A stages: 0,16K,32K ; B stages: 48K,64K,80K
    const int tid = threadIdx.x;
    const int wid = tid >> 5, lane = tid & 31;
    const int g = lane >> 2, t = lane & 3;
    const int bm = blockIdx.y * 128, bn = blockIdx.x * 128;
    const int wm = (wid & 1) * 64, wn = (wid >> 1) * 32;
    const unsigned sbase = smaddr(sm);

    const int lr = tid >> 1;                 // loader row 0..127
    const int lc = (tid & 1) * 4;            // 4 chunks each

    float acc[4][4][4];
    #pragma unroll
    for (int i = 0; i < 4; i++)
        #pragma unroll
        for (int j = 0; j < 4; j++)
            #pragma unroll
            for (int r = 0; r < 4; r++) acc[i][j][r] = 0.f;

    const __half* agp = &A[(size_t)(bm + lr) * 1024 + lc * 8];
    const __half* bgp = &Bt[(size_t)(bn + lr) * 1024 + lc * 8];
    const unsigned sA = sbase + swz(lr, lc);          // chunk-contig: +16 per chunk
    const unsigned sB = sA + 49152;

    // prologue: stages 0,1
    #pragma unroll
    for (int s = 0; s < 2; s++) {
        #pragma unroll
        for (int c = 0; c < 4; c++) {
            cp16(sA + s * 16384 + ((unsigned)((lc + c) ^ (lr & 7)) << 4) - ((unsigned)(lc ^ (lr & 7)) << 4), agp + s * 64 + c * 8);
            cp16(sB + s * 16384 + ((unsigned)((lc + c) ^ (lr & 7)) << 4) - ((unsigned)(lc ^ (lr & 7)) << 4), bgp + s * 64 + c * 8);
        }
        cp_commit();
    }
    cp_wait1();
    __syncthreads();

    const unsigned arow = ((lane >> 3) & 1) * 8 + (lane & 7);
    const unsigned ach  = (lane >> 4);
    const unsigned brow = (lane >> 4) * 8 + (lane & 7);
    const unsigned bch  = (lane >> 3) & 1;

    int buf = 0, bufn = 2;
    #pragma unroll 1
    for (int s = 0; s < GEMM_KT; s++) {
        // issue stage s+2 into buffer (s+2)%3
        if (s + 2 < GEMM_KT) {
            unsigned da = sbase + bufn * 16384;
            unsigned db = da + 49152;
            const __half* ag = agp + (s + 2) * 64;
            const __half* bg = bgp + (s + 2) * 64;
            #pragma unroll
            for (int c = 0; c < 4; c++) {
                cp16(da + swz(lr, lc + c), ag + c * 8);
                cp16(db + swz(lr, lc + c), bg + c * 8);
            }
            cp_commit();
        }

        // compute stage s
        const unsigned sa = sbase + buf * 16384;
        const unsigned sb = sa + 49152;
        #pragma unroll
        for (int kk = 0; kk < 4; kk++) {
            unsigned af[4][4], bf[2][4];
            #pragma unroll
            for (int mt = 0; mt < 4; mt++)
                ldsm4(af[mt], sa + swz(wm + mt * 16 + arow, 2 * kk + ach));
            #pragma unroll
            for (int np = 0; np < 2; np++)
                ldsm4(bf[np], sb + swz(wn + np * 16 + brow, 2 * kk + bch));
            #pragma unroll
            for (int mt = 0; mt < 4; mt++)
                #pragma unroll
                for (int nt = 0; nt < 4; nt++)
                    mma_f16(acc[mt][nt], af[mt][0], af[mt][1], af[mt][2], af[mt][3],
                            bf[nt >> 1][(nt & 1) * 2], bf[nt >> 1][(nt & 1) * 2 + 1]);
        }

        if (s + 2 < GEMM_KT)      cp_wait1();   // stage s+1 complete
        else if (s + 1 < GEMM_KT) cp_wait0();
        if (s + 1 < GEMM_KT) __syncthreads();

        buf = (buf == 2) ? 0 : buf + 1;
        bufn = (bufn == 2) ? 0 : bufn + 1;
    }

    // ---------------- epilogue ----------------
    if (mode == 0) {
        #pragma unroll
        for (int mt = 0; mt < 4; mt++) {
            int row = bm + wm + mt * 16 + g;
            #pragma unroll
            for (int nt = 0; nt < 4; nt++) {
                int col = bn + wn + nt * 8 + 2 * t;
                float b0 = bias[col], b1 = bias[col + 1];
                *(float2*)&C[(size_t)row * N + col] =
                    make_float2(acc[mt][nt][0] + b0, acc[mt][nt][1] + b1);
                *(float2*)&C[(size_t)(row + 8) * N + col] =
                    make_float2(acc[mt][nt][2] + b0, acc[mt][nt][3] + b1);
            }
        }
    } else {
        #pragma unroll
        for (int nt = 0; nt < 4; nt++) {
            int col = bn + wn + nt * 8 + 2 * t;
            int qi = col >> 10, rem = col & 1023;
            int h = rem >> 6, d0 = rem & 63;
            __half* dst = (qi == 0) ? g_qh : (qi == 1) ? g_kh : g_vh;
            float b0 = bias[col], b1 = bias[col + 1];
            #pragma unroll
            for (int mt = 0; mt < 4; mt++) {
                int row = bm + wm + mt * 16 + g;
                #pragma unroll
                for (int half = 0; half < 2; half++) {
                    int r = row + half * 8;
                    float x1 = acc[mt][nt][half * 2]     + b0;
                    float x2 = acc[mt][nt][half * 2 + 1] + b1;
                    int bb = r >> 11, tr = r & 2047;
                    size_t o = ((size_t)(bb * NH + h) * TSEQ + tr) * DK + d0;
                    if (qi < 2) {
                        float2 cs = g_rope[tr * 32 + (d0 >> 1)];
                        *(__half2*)&dst[o] = __floats2half2_rn(
                            x1 * cs.x - x2 * cs.y, x1 * cs.y + x2 * cs.x);
                    } else {
                        *(__half2*)&dst[o] = __floats2half2_rn(x1, x2);
                    }
                }
            }
        }
    }
}

// ---------------------------------------------------------------------------
// Flash attention (round-3 version): mma.sync fp16, cp.async double buffer.
// ---------------------------------------------------------------------------
__global__ __launch_bounds__(256)
void flash_h_kernel()
{
    extern __shared__ __align__(16) char sm[];
    char* Qs = sm;                               // 16KB (128x64)
    char* Ks[2] = { sm + 16384, sm + 24576 };    // 8KB each (64x64)
    char* Vs[2] = { sm + 32768, sm + 40960 };

    const int tid = threadIdx.x;
    const int wid = tid >> 5, lane = tid & 31;
    const int g = lane >> 2, t = lane & 3;
    const int qx = gridDim.x - 1 - blockIdx.x;   // big tiles first
    const int bh = blockIdx.y;
    const int b = bh >> 4, h = bh & 15;
    const int qb = qx * 128;

    const __half* Qp = g_qh + (size_t)bh * TSEQ * DK;
    const __half* Kp = g_kh + (size_t)bh * TSEQ * DK;
    const __half* Vp = g_vh + (size_t)bh * TSEQ * DK;

    const int lr  = tid >> 1;
    const int lc  = (tid & 1) * 4;
    const int kvr = tid >> 2;
    const int kvc = (tid & 3) * 2;

    {
        unsigned sq = smaddr(Qs);
        #pragma unroll
        for (int c = 0; c < 4; c++)
            cp16(sq + swz(lr, lc + c), &Qp[(size_t)(qb + lr) * DK + (lc + c) * 8]);
        cp_commit();
        unsigned sk = smaddr(Ks[0]), sv = smaddr(Vs[0]);
        #pragma unroll
        for (int c = 0; c < 2; c++) {
            cp16(sk + swz(kvr, kvc + c), &Kp[(size_t)kvr * DK + (kvc + c) * 8]);
            cp16(sv + swz(kvr, kvc + c), &Vp[(size_t)kvr * DK + (kvc + c) * 8]);
        }
        cp_commit();
    }

    unsigned qa[4][4];
    float o[8][4];
    #pragma unroll
    for (int nt = 0; nt < 8; nt++)
        #pragma unroll
        for (int r = 0; r < 4; r++) o[nt][r] = 0.f;
    float m0 = -INFINITY, m1 = -INFINITY, l0 = 0.f, l1 = 0.f;
    const float scale = 0.125f;
    const int tiles = 2 * qx + 2;

    const unsigned arow = ((lane >> 3) & 1) * 8 + (lane & 7);
    const unsigned ach  = (lane >> 4);
    const unsigned brow = (lane >> 4) * 8 + (lane & 7);
    const unsigned bch  = (lane >> 3) & 1;

    for (int j = 0; j < tiles; j++) {
        __syncthreads();
        if (j + 1 < tiles) {
            int st = (j + 1) & 1, s0 = (j + 1) * 64;
            unsigned sk = smaddr(Ks[st]), sv = smaddr(Vs[st]);
            #pragma unroll
            for (int c = 0; c < 2; c++) {
                cp16(sk + swz(kvr, kvc + c), &Kp[(size_t)(s0 + kvr) * DK + (kvc + c) * 8]);
                cp16(sv + swz(kvr, kvc + c), &Vp[(size_t)(s0 + kvr) * DK + (kvc + c) * 8]);
            }
            cp_commit();
            cp_wait1();
        } else {
            cp_wait0();
        }
        __syncthreads();

        if (j == 0) {
            unsigned sq = smaddr(Qs);
            #pragma unroll
            for (int kk = 0; kk < 4; kk++)
                ldsm4(qa[kk], sq + swz(wid * 16 + arow, 2 * kk + ach));
        }

        const unsigned sk = smaddr(Ks[j & 1]), sv = smaddr(Vs[j & 1]);

        float sa[8][4];
        #pragma unroll
        for (int nt = 0; nt < 8; nt++)
            #pragma unroll
            for (int r = 0; r < 4; r++) sa[nt][r] = 0.f;
        #pragma unroll
        for (int kk = 0; kk < 4; kk++) {
            unsigned kf[4][4];
            #pragma unroll
            for (int np = 0; np < 4; np++)
                ldsm4(kf[np], sk + swz(np * 16 + brow, 2 * kk + bch));
            #pragma unroll
            for (int nt = 0; nt < 8; nt++)
                mma_f16(sa[nt], qa[kk][0], qa[kk][1], qa[kk][2], qa[kk][3],
                        kf[nt >> 1][(nt & 1) * 2], kf[nt >> 1][(nt & 1) * 2 + 1]);
        }

        if (j >= 2 * qx) {
            int row0 = qb + wid * 16 + g, row1 = row0 + 8;
            #pragma unroll
            for (int nt = 0; nt < 8; nt++) {
                int c = j * 64 + nt * 8 + 2 * t;
                if (c > row0)     sa[nt][0] = -1e30f;
                if (c + 1 > row0) sa[nt][1] = -1e30f;
                if (c > row1)     sa[nt][2] = -1e30f;
                if (c + 1 > row1) sa[nt][3] = -1e30f;
            }
        }

        float rm0 = -INFINITY, rm1 = -INFINITY;
        #pragma unroll
        for (int nt = 0; nt < 8; nt++) {
            rm0 = fmaxf(rm0, fmaxf(sa[nt][0], sa[nt][1]));
            rm1 = fmaxf(rm1, fmaxf(sa[nt][2], sa[nt][3]));
        }
        rm0 = fmaxf(rm0, __shfl_xor_sync(0xffffffffu, rm0, 1));
        rm0 = fmaxf(rm0, __shfl_xor_sync(0xffffffffu, rm0, 2));
        rm1 = fmaxf(rm1, __shfl_xor_sync(0xffffffffu, rm1, 1));
        rm1 = fmaxf(rm1, __shfl_xor_sync(0xffffffffu, rm1, 2));

        float M0 = fmaxf(m0, rm0), M1 = fmaxf(m1, rm1);
        float a0 = __expf((m0 - M0) * scale);
        float a1 = __expf((m1 - M1) * scale);

        unsigned pa[8], pb[8];
        float rs0 = 0.f, rs1 = 0.f;
        #pragma unroll
        for (int nt = 0; nt < 8; nt++) {
            float p00 = __expf((sa[nt][0] - M0) * scale);
            float p01 = __expf((sa[nt][1] - M0) * scale);
            float p10 = __expf((sa[nt][2] - M1) * scale);
            float p11 = __expf((sa[nt][3] - M1) * scale);
            rs0 += p00 + p01;
            rs1 += p10 + p11;
            pa[nt] = pack_h2(p00, p01);
            pb[nt] = pack_h2(p10, p11);
        }
        rs0 += __shfl_xor_sync(0xffffffffu, rs0, 1);
        rs0 += __shfl_xor_sync(0xffffffffu, rs0, 2);
        rs1 += __shfl_xor_sync(0xffffffffu, rs1, 1);
        rs1 += __shfl_xor_sync(0xffffffffu, rs1, 2);
        l0 = l0 * a0 + rs0;
        l1 = l1 * a1 + rs1;
        m0 = M0; m1 = M1;

        #pragma unroll
        for (int nt = 0; nt < 8; nt++) {
            o[nt][0] *= a0; o[nt][1] *= a0;
            o[nt][2] *= a1; o[nt][3] *= a1;
        }

        #pragma unroll
        for (int kk = 0; kk < 4; kk++) {
            unsigned vf[4][4];
            #pragma unroll
            for (int np = 0; np < 4; np++)
                ldsm4t(vf[np], sv + swz(16 * kk + arow, np * 2 + ach));
            unsigned A0 = pa[2 * kk], A1 = pb[2 * kk];
            unsigned A2 = pa[2 * kk + 1], A3 = pb[2 * kk + 1];
            #pragma unroll
            for (int nt = 0; nt < 8; nt++)
                mma_f16(o[nt], A0, A1, A2, A3,
                        vf[nt >> 1][(nt & 1) * 2], vf[nt >> 1][(nt & 1) * 2 + 1]);
        }
    }

    float i0 = 1.f / l0, i1 = 1.f / l1;
    int row0 = qb + wid * 16 + g;
    size_t gr0 = (size_t)(b * TSEQ + row0) * DMODEL;
    size_t gr1 = (size_t)(b * TSEQ + row0 + 8) * DMODEL;
    #pragma unroll
    for (int nt = 0; nt < 8; nt++) {
        int col = h * DK + nt * 8 + 2 * t;
        *(__half2*)&g_attn[gr0 + col] = __floats2half2_rn(o[nt][0] * i0, o[nt][1] * i0);
        *(__half2*)&g_attn[gr1 + col] = __floats2half2_rn(o[nt][2] * i1, o[nt][3] * i1);
    }
}

// ---------------------------------------------------------------------------
extern "C" void kernel_launch(void* const* d_in, const int* in_sizes, int n_in,
                              void* d_out, int out_size)
{
    const float* x     = (const float*)d_in[0];
    const float* W_qkv = (const float*)d_in[1];
    const float* b_qkv = (const float*)d_in[2];
    const float* W_out = (const float*)d_in[3];
    const float* b_out = (const float*)d_in[4];
    float* out = (float*)d_out;

    __half* xh;     cudaGetSymbolAddress((void**)&xh,     g_xh);
    __half* wqkvT;  cudaGetSymbolAddress((void**)&wqkvT,  g_wqkvT);
    __half* woutT;  cudaGetSymbolAddress((void**)&woutT,  g_woutT);
    __half* attn;   cudaGetSymbolAddress((void**)&attn,   g_attn);

    const int gemm_smem = 98304;   // 3 stages x (16K A + 16K B)
    cudaFuncSetAttribute(gemm_h_kernel,
                         cudaFuncAttributeMaxDynamicSharedMemorySize, gemm_smem);
    cudaFuncSetAttribute(flash_h_kernel,
                         cudaFuncAttributeMaxDynamicSharedMemorySize, 49152);

    cast_x_kernel<<<(BT * DMODEL / 2 + 255) / 256, 256>>>(x);
    rope_table_kernel<<<(TSEQ * 32 + 255) / 256, 256>>>();
    {
        dim3 grid(3 * DMODEL / 32, DMODEL / 32), blk(32, 8);
        transpose_cast_kernel<<<grid, blk>>>(W_qkv, wqkvT, 3 * DMODEL);
    }
    {
        dim3 grid(DMODEL / 32, DMODEL / 32), blk(32, 8);
        transpose_cast_kernel<<<grid, blk>>>(W_out, woutT, DMODEL);
    }

    // 1) QKV projection + fused bias/RoPE/split (mode 1)
    {
        dim3 grid(3 * DMODEL / 128, BT / 128);
        gemm_h_kernel<<<grid, 256, gemm_smem>>>(xh, wqkvT, b_qkv, nullptr,
                                                BT, 3 * DMODEL, 1);
    }

    // 2) flash attention
    {
        dim3 grid(TSEQ / 128, BSZ * NH);
        flash_h_kernel<<<grid, 256, 49152>>>();
    }

    // 3) output projection (mode 0) -> d_out
    {
        dim3 grid(DMODEL / 128, BT / 128);
        gemm_h_kernel<<<grid, 256, gemm_smem>>>(attn, woutT, b_out, out,
                                                BT, DMODEL, 0);
    }
}